// round 12
// baseline (speedup 1.0000x reference)
#include <cuda_runtime.h>
#include <cuda_bf16.h>
#include <cstdint>

#define B_      16384
#define D_      256
#define NSTEPS_ 5
#define BD      (B_*D_)

// ---------------------------------------------------------------------------
// Persistent state (re-initialized on every kernel_launch -> deterministic).
__device__ __align__(16) float g_xa [BD];
__device__ __align__(16) float g_vx [BD];
__device__ __align__(16) float g_vxd[BD];
__device__ __align__(16) float g_p  [BD];
__device__ __align__(16) __nv_bfloat16 g_xbf [BD];   // current binary state (exact)
__device__ __align__(16) __nv_bfloat16 g_xdbf[BD];   // proposal x_delta (exact)
// W 3-level bf16 split for the single initial dense GEMM.
__device__ __align__(16) __nv_bfloat16 g_Wt[3 * 256 * 256];

// ---------------------------------------------------------------------------
__device__ __forceinline__ void cpasync16(uint32_t dst, const void* src) {
    asm volatile("cp.async.ca.shared.global [%0], [%1], 16;" :: "r"(dst), "l"(src));
}
__device__ __forceinline__ void ldsm4(uint32_t& r0, uint32_t& r1, uint32_t& r2,
                                      uint32_t& r3, uint32_t addr) {
    asm volatile("ldmatrix.sync.aligned.m8n8.x4.shared.b16 {%0,%1,%2,%3}, [%4];"
                 : "=r"(r0), "=r"(r1), "=r"(r2), "=r"(r3) : "r"(addr));
}

// flip probability: decision-critical, bit-identical to all passing rounds.
__device__ __forceinline__ float flip_p(float vx, float bv, float ga, float s) {
    float d  = ((vx + bv) * s) * 0.5f;
    float gm = d - (ga * 0.5f) * s;
    float t  = gm - 2.5f;
    return 1.0f / (1.0f + expf(-t));
}

// Division-free polynomial log (feeds la only).
__device__ __forceinline__ float fast_log(float a) {
    int ix = __float_as_int(a);
    int e  = (ix - 0x3f3504f3) & 0xff800000;
    float m  = __int_as_float(ix - e);
    float kf = (float)(e >> 23);
    float f  = m - 1.0f;
    float r  = 0.09090909f;
    r = fmaf(r, f, -0.1f);
    r = fmaf(r, f,  0.11111111f);
    r = fmaf(r, f, -0.125f);
    r = fmaf(r, f,  0.14285714f);
    r = fmaf(r, f, -0.16666667f);
    r = fmaf(r, f,  0.2f);
    r = fmaf(r, f, -0.25f);
    r = fmaf(r, f,  0.33333333f);
    r = fmaf(r, f, -0.5f);
    r = fmaf(r, f,  1.0f);
    return fmaf(kf, 0.6931472f, r * f);
}

// Sparse rank-~20 update: corr[n] += sum over flipped d of s_d * W[d][n].
// fm: per-lane 8-bit flip mask (bit j = element lane*8+j flipped).
// sm: per-lane 8-bit sign mask (bit j = x==1 there, i.e. s=-1).
__device__ __forceinline__ void sparse_corr(uint32_t fm, uint32_t sm,
                                            const float* __restrict__ Wm,
                                            int lane, float corr[8]) {
    uint32_t packed = fm | (sm << 8);
    #pragma unroll 1
    for (int L = 0; L < 32; L++) {
        uint32_t pk = __shfl_sync(0xffffffffu, packed, L);
        uint32_t f  = pk & 0xffu;
        uint32_t sb = pk >> 8;
        while (f) {
            int r = __ffs(f) - 1;
            f &= f - 1;
            int d = L * 8 + r;
            float sgn = ((sb >> r) & 1u) ? -1.0f : 1.0f;
            float4 w0 = __ldg((const float4*)&Wm[d * 256 + lane * 8]);
            float4 w1 = __ldg((const float4*)&Wm[d * 256 + lane * 8 + 4]);
            corr[0] = fmaf(sgn, w0.x, corr[0]);
            corr[1] = fmaf(sgn, w0.y, corr[1]);
            corr[2] = fmaf(sgn, w0.z, corr[2]);
            corr[3] = fmaf(sgn, w0.w, corr[3]);
            corr[4] = fmaf(sgn, w1.x, corr[4]);
            corr[5] = fmaf(sgn, w1.y, corr[5]);
            corr[6] = fmaf(sgn, w1.z, corr[6]);
            corr[7] = fmaf(sgn, w1.w, corr[7]);
        }
    }
}

__global__ void kinit(const float* __restrict__ x_in, const float* __restrict__ xa_in) {
    int i4 = (blockIdx.x * blockDim.x + threadIdx.x) * 4;
    if (i4 >= BD) return;
    float4 x = *(const float4*)&x_in[i4];
    *(float4*)&g_xa[i4] = *(const float4*)&xa_in[i4];
    __nv_bfloat16 xb[4] = { __float2bfloat16(x.x), __float2bfloat16(x.y),
                            __float2bfloat16(x.z), __float2bfloat16(x.w) };
    *(uint2*)&g_xbf[i4] = *(uint2*)xb;
}

__global__ void kprep(const float* __restrict__ Wm_in) {
    int k = threadIdx.x;
    int n = blockIdx.x;
    float w = Wm_in[k * 256 + n];
    __nv_bfloat16 h = __float2bfloat16(w);
    float r1 = w - __bfloat162float(h);
    __nv_bfloat16 m = __float2bfloat16(r1);
    float r2 = r1 - __bfloat162float(m);
    __nv_bfloat16 l = __float2bfloat16(r2);
    size_t base = (size_t)n * 256 + k;
    g_Wt[base]             = h;
    g_Wt[65536 + base]     = m;
    g_Wt[2 * 65536 + base] = l;
}

// ---------------------------------------------------------------------------
// Initial dense GEMM (identical to R10/R11): mma.sync + ldmatrix, XOR swizzle.
#define KC 32
#define ABUF_BYTES 8192
#define BBUF_BYTES 4096
#define BUF_BYTES  (ABUF_BYTES + 3 * BBUF_BYTES)
__global__ __launch_bounds__(256) void gemm_tc(const __nv_bfloat16* __restrict__ Abf,
                                               float* __restrict__ C) {
    __shared__ __align__(16) uint8_t smemraw[2][BUF_BYTES];

    const int t    = threadIdx.x;
    const int wid  = t >> 5;
    const int lane = t & 31;
    const int g    = lane >> 2;
    const int tg   = lane & 3;
    const int m0   = blockIdx.x * 128;
    const int n0   = blockIdx.y * 64;

    const uint32_t smem0 = (uint32_t)__cvta_generic_to_shared(&smemraw[0][0]);
    const uint32_t smem1 = (uint32_t)__cvta_generic_to_shared(&smemraw[1][0]);

    float acc[8][4];
    #pragma unroll
    for (int nt = 0; nt < 8; nt++)
        #pragma unroll
        for (int r = 0; r < 4; r++) acc[nt][r] = 0.0f;

    auto ldchunk = [&](int c, int buf) {
        int k0 = c * KC;
        uint32_t base = buf ? smem1 : smem0;
        #pragma unroll
        for (int i = 0; i < 2; i++) {
            int u = t + 256 * i;
            int m = u >> 2, q = u & 3;
            uint32_t dst = base + m * 64 + ((q ^ ((m >> 1) & 3)) << 4);
            cpasync16(dst, &Abf[(size_t)(m0 + m) * 256 + k0 + q * 8]);
        }
        #pragma unroll
        for (int i = 0; i < 3; i++) {
            int u = t + 256 * i;
            int l = u >> 8, rem = u & 255;
            int n = rem >> 2, q = rem & 3;
            uint32_t dst = base + ABUF_BYTES + l * BBUF_BYTES
                         + n * 64 + ((q ^ ((n >> 1) & 3)) << 4);
            cpasync16(dst, &g_Wt[(size_t)l * 65536 + (size_t)(n0 + n) * 256 + k0 + q * 8]);
        }
        asm volatile("cp.async.commit_group;");
    };

    const int rL   = lane & 15;
    const int usel = lane >> 4;
    const int mA   = wid * 16 + rL;
    const int sA   = (mA >> 1) & 3;
    const int sB   = (rL >> 1) & 3;

    ldchunk(0, 0);

    #pragma unroll 1
    for (int c = 0; c < 256 / KC; c++) {
        if (c + 1 < 256 / KC) {
            ldchunk(c + 1, (c + 1) & 1);
            asm volatile("cp.async.wait_group 1;");
        } else {
            asm volatile("cp.async.wait_group 0;");
        }
        __syncthreads();

        const uint32_t base = (c & 1) ? smem1 : smem0;
        const uint32_t arow = base + mA * 64;

        #pragma unroll
        for (int kt = 0; kt < 2; kt++) {
            const int ku = (kt << 1) | usel;
            uint32_t a0, a1, a2, a3;
            ldsm4(a0, a1, a2, a3, arow + ((ku ^ sA) << 4));
            #pragma unroll
            for (int l = 0; l < 3; l++) {
                const uint32_t bbase = base + ABUF_BYTES + l * BBUF_BYTES
                                     + ((ku ^ sB) << 4);
                #pragma unroll
                for (int np = 0; np < 4; np++) {
                    uint32_t b0, b1, b2, b3;
                    ldsm4(b0, b1, b2, b3, bbase + (np * 16 + rL) * 64);
                    asm volatile(
                        "mma.sync.aligned.m16n8k16.row.col.f32.bf16.bf16.f32 "
                        "{%0,%1,%2,%3}, {%4,%5,%6,%7}, {%8,%9}, {%0,%1,%2,%3};"
                        : "+f"(acc[2*np][0]), "+f"(acc[2*np][1]),
                          "+f"(acc[2*np][2]), "+f"(acc[2*np][3])
                        : "r"(a0), "r"(a1), "r"(a2), "r"(a3), "r"(b0), "r"(b2));
                    asm volatile(
                        "mma.sync.aligned.m16n8k16.row.col.f32.bf16.bf16.f32 "
                        "{%0,%1,%2,%3}, {%4,%5,%6,%7}, {%8,%9}, {%0,%1,%2,%3};"
                        : "+f"(acc[2*np+1][0]), "+f"(acc[2*np+1][1]),
                          "+f"(acc[2*np+1][2]), "+f"(acc[2*np+1][3])
                        : "r"(a0), "r"(a1), "r"(a2), "r"(a3), "r"(b1), "r"(b3));
                }
            }
        }
        __syncthreads();
    }

    #pragma unroll
    for (int nt = 0; nt < 8; nt++) {
        size_t row = (size_t)(m0 + wid * 16 + g);
        int    col = n0 + nt * 8 + tg * 2;
        *(float2*)&C[row * 256 + col]       = make_float2(acc[nt][0], acc[nt][1]);
        *(float2*)&C[(row + 8) * 256 + col] = make_float2(acc[nt][2], acc[nt][3]);
    }
}

// ---------------------------------------------------------------------------
// Phase 1: warp per row. Proposal for step 0 + sparse vxd = vx + corrections.
__global__ __launch_bounds__(256) void phase1(const float* __restrict__ rr_s,
                                              const float* __restrict__ bvec,
                                              const float* __restrict__ Wm) {
    int gwarp = (blockIdx.x * blockDim.x + threadIdx.x) >> 5;
    int lane  = threadIdx.x & 31;
    if (gwarp >= B_) return;
    size_t base  = (size_t)gwarp * 256 + lane * 8;
    int    dbase = lane * 8;

    __nv_bfloat16 xb[8];
    *(uint4*)xb = *(const uint4*)&g_xbf[base];
    float xav[8], vxv[8], rrv[8], bvv[8];
    #pragma unroll
    for (int h = 0; h < 2; h++) {
        *(float4*)&xav[4*h] = __ldg((const float4*)&g_xa [base + 4*h]);
        *(float4*)&vxv[4*h] = __ldg((const float4*)&g_vx [base + 4*h]);
        *(float4*)&rrv[4*h] = __ldg((const float4*)&rr_s [base + 4*h]);
        *(float4*)&bvv[4*h] = __ldg((const float4*)&bvec [dbase + 4*h]);
    }

    float pv[8];
    __nv_bfloat16 xdb[8];
    uint32_t fm = 0, sm = 0;
    #pragma unroll
    for (int j = 0; j < 8; j++) {
        float x  = __bfloat162float(xb[j]);
        float s  = 1.0f - 2.0f * x;
        float ga = (x - xav[j]) / 1.0e4f;
        float p  = flip_p(vxv[j], bvv[j], ga, s);
        int flip = rrv[j] < p;
        float xd = flip ? (x + s) : x;
        pv[j]  = p;
        xdb[j] = __float2bfloat16(xd);
        if (flip)     fm |= 1u << j;
        if (x > 0.5f) sm |= 1u << j;
    }
    *(uint4*)&g_xdbf[base] = *(uint4*)xdb;
    #pragma unroll
    for (int h = 0; h < 2; h++)
        *(float4*)&g_p[base + 4*h] = *(float4*)&pv[4*h];

    float corr[8] = {0,0,0,0,0,0,0,0};
    sparse_corr(fm, sm, Wm, lane, corr);
    float vxd[8];
    #pragma unroll
    for (int j = 0; j < 8; j++) vxd[j] = vxv[j] + corr[j];
    #pragma unroll
    for (int h = 0; h < 2; h++)
        *(float4*)&g_vxd[base + 4*h] = *(float4*)&vxd[4*h];
}

__device__ __forceinline__ double wsumd(double v) {
    #pragma unroll
    for (int off = 16; off; off >>= 1) v += __shfl_xor_sync(0xffffffffu, v, off, 32);
    return v;
}

// Phase 2: MH accept + state select + next proposal + sparse next vxd.
__global__ __launch_bounds__(256) void phase2(const float* __restrict__ noise_s,
                                              const float* __restrict__ u_s,
                                              const float* __restrict__ rr_next,
                                              const float* __restrict__ bvec,
                                              const float* __restrict__ Wm,
                                              float* __restrict__ out, int last) {
    int gwarp = (blockIdx.x * blockDim.x + threadIdx.x) >> 5;
    int lane  = threadIdx.x & 31;
    if (gwarp >= B_) return;
    size_t base  = (size_t)gwarp * 256 + lane * 8;
    int    dbase = lane * 8;

    __nv_bfloat16 xb[8], xdb[8];
    *(uint4*)xb  = *(const uint4*)&g_xbf [base];
    *(uint4*)xdb = *(const uint4*)&g_xdbf[base];

    float uu = __ldg(&u_s[gwarp]);                 // early
    float xav[8], vxv[8], vxdv[8], pv[8], nzv[8], bvv[8], rrv[8];
    #pragma unroll
    for (int h = 0; h < 2; h++) {
        *(float4*)&xav [4*h] = __ldg((const float4*)&g_xa [base + 4*h]);
        *(float4*)&vxv [4*h] = __ldg((const float4*)&g_vx [base + 4*h]);
        *(float4*)&vxdv[4*h] = __ldg((const float4*)&g_vxd[base + 4*h]);
        *(float4*)&pv  [4*h] = __ldg((const float4*)&g_p  [base + 4*h]);
        *(float4*)&nzv [4*h] = __ldg((const float4*)&noise_s[base + 4*h]);
        *(float4*)&bvv [4*h] = __ldg((const float4*)&bvec [dbase + 4*h]);
    }
    if (!last) {
        #pragma unroll
        for (int h = 0; h < 2; h++)
            *(float4*)&rrv[4*h] = __ldg((const float4*)&rr_next[base + 4*h]);
    }

    float xv[8], xdv[8], xdav[8], p2v[8];
    double q = 0.0;

    #pragma unroll
    for (int j = 0; j < 8; j++) {
        float x  = __bfloat162float(xb[j]);
        float xd = __bfloat162float(xdb[j]);
        float xa = xav[j], vx = vxv[j], vxd = vxdv[j];
        float p = pv[j], nz = nzv[j], bv = bvv[j];

        float ga  = (x - xa) / 1.0e4f;
        float ind = (x != xd) ? 1.0f : 0.0f;
        float xda = (xa + 0.25f * ga) + 0.70710678118654752f * nz;

        float s2  = 1.0f - 2.0f * xd;
        float ga2 = (xd - xda) / 1.0e4f;
        float p2  = flip_p(vxd, bv, ga2, s2);

        float a1 = (ind != 0.0f) ? (p  + 1e-10f) : ((1.0f - p)  + 1e-10f);
        float a2 = (ind != 0.0f) ? (p2 + 1e-10f) : ((1.0f - p2) + 1e-10f);
        float t_log = fast_log(a2) - fast_log(a1);

        float dc = x  - xa;
        float dn = xd - xda;
        float t_m = ((0.5f * (vxd * xd) + bv * xd) - (dn * dn) * 5e-5f)
                  - ((0.5f * (vx  * x ) + bv * x ) - (dc * dc) * 5e-5f);

        float ff = xda - (xa + 0.25f * ga);
        float fr = xa  - (xda + 0.25f * ga2);
        float t_q = ff * ff - fr * fr;

        q += (double)(t_log + t_m + t_q);

        xv[j] = x; xdv[j] = xd; xdav[j] = xda; p2v[j] = p2;
    }

    double la = wsumd(q);
    int accept = la > log((double)uu);

    if (last) {
        float o1[8], o2[8];
        #pragma unroll
        for (int j = 0; j < 8; j++) {
            o1[j] = accept ? xdv[j]  : xv[j];
            o2[j] = accept ? xdav[j] : xav[j];
        }
        #pragma unroll
        for (int h = 0; h < 2; h++) {
            *(float4*)&out[base + 4*h]      = *(float4*)&o1[4*h];
            *(float4*)&out[BD + base + 4*h] = *(float4*)&o2[4*h];
        }
        return;
    }

    if (accept) {
        *(uint4*)&g_xbf[base] = *(uint4*)xdb;
        #pragma unroll
        for (int h = 0; h < 2; h++) {
            *(float4*)&g_xa[base + 4*h] = *(float4*)&xdav[4*h];
            *(float4*)&g_vx[base + 4*h] = *(float4*)&vxdv[4*h];
            *(float4*)&g_p [base + 4*h] = *(float4*)&p2v [4*h];
        }
    }

    // Next proposal (p_next = accept ? p2 : p, bit-identical) + flip masks.
    float vxn[8];
    __nv_bfloat16 xdn[8];
    uint32_t fm = 0, sm = 0;
    #pragma unroll
    for (int j = 0; j < 8; j++) {
        float xn = accept ? xdv[j] : xv[j];
        float pn = accept ? p2v[j] : pv[j];
        vxn[j]   = accept ? vxdv[j] : vxv[j];
        float s  = 1.0f - 2.0f * xn;
        int flip = rrv[j] < pn;
        float xdnf = flip ? (xn + s) : xn;
        xdn[j] = __float2bfloat16(xdnf);
        if (flip)      fm |= 1u << j;
        if (xn > 0.5f) sm |= 1u << j;
    }
    *(uint4*)&g_xdbf[base] = *(uint4*)xdn;

    // Sparse vxd for the next step.
    float corr[8] = {0,0,0,0,0,0,0,0};
    sparse_corr(fm, sm, Wm, lane, corr);
    float vxdn[8];
    #pragma unroll
    for (int j = 0; j < 8; j++) vxdn[j] = vxn[j] + corr[j];
    #pragma unroll
    for (int h = 0; h < 2; h++)
        *(float4*)&g_vxd[base + 4*h] = *(float4*)&vxdn[4*h];
}

// ---------------------------------------------------------------------------
extern "C" void kernel_launch(void* const* d_in, const int* in_sizes, int n_in,
                              void* d_out, int out_size) {
    (void)in_sizes; (void)n_in; (void)out_size;
    const float* x_in  = (const float*)d_in[0];
    const float* xa_in = (const float*)d_in[1];
    const float* Wm    = (const float*)d_in[2];
    const float* bvec  = (const float*)d_in[3];
    const float* rr    = (const float*)d_in[4];
    const float* noise = (const float*)d_in[5];
    const float* u     = (const float*)d_in[6];
    float* out = (float*)d_out;

    __nv_bfloat16* xbf_p;  cudaGetSymbolAddress((void**)&xbf_p,  g_xbf);
    float* vx_p;  cudaGetSymbolAddress((void**)&vx_p,  g_vx);

    kinit<<<BD / 1024, 256>>>(x_in, xa_in);
    kprep<<<256, 256>>>(Wm);
    gemm_tc<<<dim3(B_ / 128, 256 / 64), 256>>>(xbf_p, vx_p);   // initial vx = x @ W
    phase1<<<B_ / 8, 256>>>(rr, bvec, Wm);                     // proposal 0 + sparse vxd
    for (int s = 0; s < NSTEPS_; s++) {
        int lastf = (s == NSTEPS_ - 1);
        phase2<<<B_ / 8, 256>>>(noise + (size_t)s * BD, u + (size_t)s * B_,
                                lastf ? (const float*)d_in[4]
                                      : rr + (size_t)(s + 1) * BD,
                                bvec, Wm, out, lastf);
    }
}

// round 13
// speedup vs baseline: 1.5548x; 1.5548x over previous
#include <cuda_runtime.h>
#include <cuda_bf16.h>
#include <cstdint>

#define B_      16384
#define D_      256
#define NSTEPS_ 5
#define BD      (B_*D_)

// ---------------------------------------------------------------------------
// Persistent state across launches (re-initialized every launch).
__device__ __align__(16) float g_vx [BD];            // initial x @ W (dense GEMM)
__device__ __align__(16) __nv_bfloat16 g_xbf[BD];    // bf16 mirror of x for GEMM
__device__ __align__(16) __nv_bfloat16 g_Wt[3 * 256 * 256];  // 3-level split W

// ---------------------------------------------------------------------------
__device__ __forceinline__ void cpasync16(uint32_t dst, const void* src) {
    asm volatile("cp.async.ca.shared.global [%0], [%1], 16;" :: "r"(dst), "l"(src));
}
__device__ __forceinline__ void ldsm4(uint32_t& r0, uint32_t& r1, uint32_t& r2,
                                      uint32_t& r3, uint32_t addr) {
    asm volatile("ldmatrix.sync.aligned.m8n8.x4.shared.b16 {%0,%1,%2,%3}, [%4];"
                 : "=r"(r0), "=r"(r1), "=r"(r2), "=r"(r3) : "r"(addr));
}

// flip probability: decision-critical, bit-identical to all passing rounds.
__device__ __forceinline__ float flip_p(float vx, float bv, float ga, float s) {
    float d  = ((vx + bv) * s) * 0.5f;
    float gm = d - (ga * 0.5f) * s;
    float t  = gm - 2.5f;
    return 1.0f / (1.0f + expf(-t));
}

// Division-free polynomial log (feeds la only).
__device__ __forceinline__ float fast_log(float a) {
    int ix = __float_as_int(a);
    int e  = (ix - 0x3f3504f3) & 0xff800000;
    float m  = __int_as_float(ix - e);
    float kf = (float)(e >> 23);
    float f  = m - 1.0f;
    float r  = 0.09090909f;
    r = fmaf(r, f, -0.1f);
    r = fmaf(r, f,  0.11111111f);
    r = fmaf(r, f, -0.125f);
    r = fmaf(r, f,  0.14285714f);
    r = fmaf(r, f, -0.16666667f);
    r = fmaf(r, f,  0.2f);
    r = fmaf(r, f, -0.25f);
    r = fmaf(r, f,  0.33333333f);
    r = fmaf(r, f, -0.5f);
    r = fmaf(r, f,  1.0f);
    return fmaf(kf, 0.6931472f, r * f);
}

__device__ __forceinline__ double wsumd(double v) {
    #pragma unroll
    for (int off = 16; off; off >>= 1) v += __shfl_xor_sync(0xffffffffu, v, off, 32);
    return v;
}

__global__ void kinit(const float* __restrict__ x_in) {
    int i4 = (blockIdx.x * blockDim.x + threadIdx.x) * 4;
    if (i4 >= BD) return;
    float4 x = *(const float4*)&x_in[i4];
    __nv_bfloat16 xb[4] = { __float2bfloat16(x.x), __float2bfloat16(x.y),
                            __float2bfloat16(x.z), __float2bfloat16(x.w) };
    *(uint2*)&g_xbf[i4] = *(uint2*)xb;
}

__global__ void kprep(const float* __restrict__ Wm_in) {
    int k = threadIdx.x;
    int n = blockIdx.x;
    float w = Wm_in[k * 256 + n];
    __nv_bfloat16 h = __float2bfloat16(w);
    float r1 = w - __bfloat162float(h);
    __nv_bfloat16 m = __float2bfloat16(r1);
    float r2 = r1 - __bfloat162float(m);
    __nv_bfloat16 l = __float2bfloat16(r2);
    size_t base = (size_t)n * 256 + k;
    g_Wt[base]             = h;
    g_Wt[65536 + base]     = m;
    g_Wt[2 * 65536 + base] = l;
}

// ---------------------------------------------------------------------------
// Initial dense GEMM (identical to R10-R12): mma.sync + ldmatrix, XOR swizzle.
#define KC 32
#define ABUF_BYTES 8192
#define BBUF_BYTES 4096
#define BUF_BYTES  (ABUF_BYTES + 3 * BBUF_BYTES)
__global__ __launch_bounds__(256) void gemm_tc(const __nv_bfloat16* __restrict__ Abf,
                                               float* __restrict__ C) {
    __shared__ __align__(16) uint8_t smemraw[2][BUF_BYTES];

    const int t    = threadIdx.x;
    const int wid  = t >> 5;
    const int lane = t & 31;
    const int g    = lane >> 2;
    const int tg   = lane & 3;
    const int m0   = blockIdx.x * 128;
    const int n0   = blockIdx.y * 64;

    const uint32_t smem0 = (uint32_t)__cvta_generic_to_shared(&smemraw[0][0]);
    const uint32_t smem1 = (uint32_t)__cvta_generic_to_shared(&smemraw[1][0]);

    float acc[8][4];
    #pragma unroll
    for (int nt = 0; nt < 8; nt++)
        #pragma unroll
        for (int r = 0; r < 4; r++) acc[nt][r] = 0.0f;

    auto ldchunk = [&](int c, int buf) {
        int k0 = c * KC;
        uint32_t base = buf ? smem1 : smem0;
        #pragma unroll
        for (int i = 0; i < 2; i++) {
            int u = t + 256 * i;
            int m = u >> 2, q = u & 3;
            uint32_t dst = base + m * 64 + ((q ^ ((m >> 1) & 3)) << 4);
            cpasync16(dst, &Abf[(size_t)(m0 + m) * 256 + k0 + q * 8]);
        }
        #pragma unroll
        for (int i = 0; i < 3; i++) {
            int u = t + 256 * i;
            int l = u >> 8, rem = u & 255;
            int n = rem >> 2, q = rem & 3;
            uint32_t dst = base + ABUF_BYTES + l * BBUF_BYTES
                         + n * 64 + ((q ^ ((n >> 1) & 3)) << 4);
            cpasync16(dst, &g_Wt[(size_t)l * 65536 + (size_t)(n0 + n) * 256 + k0 + q * 8]);
        }
        asm volatile("cp.async.commit_group;");
    };

    const int rL   = lane & 15;
    const int usel = lane >> 4;
    const int mA   = wid * 16 + rL;
    const int sA   = (mA >> 1) & 3;
    const int sB   = (rL >> 1) & 3;

    ldchunk(0, 0);

    #pragma unroll 1
    for (int c = 0; c < 256 / KC; c++) {
        if (c + 1 < 256 / KC) {
            ldchunk(c + 1, (c + 1) & 1);
            asm volatile("cp.async.wait_group 1;");
        } else {
            asm volatile("cp.async.wait_group 0;");
        }
        __syncthreads();

        const uint32_t base = (c & 1) ? smem1 : smem0;
        const uint32_t arow = base + mA * 64;

        #pragma unroll
        for (int kt = 0; kt < 2; kt++) {
            const int ku = (kt << 1) | usel;
            uint32_t a0, a1, a2, a3;
            ldsm4(a0, a1, a2, a3, arow + ((ku ^ sA) << 4));
            #pragma unroll
            for (int l = 0; l < 3; l++) {
                const uint32_t bbase = base + ABUF_BYTES + l * BBUF_BYTES
                                     + ((ku ^ sB) << 4);
                #pragma unroll
                for (int np = 0; np < 4; np++) {
                    uint32_t b0, b1, b2, b3;
                    ldsm4(b0, b1, b2, b3, bbase + (np * 16 + rL) * 64);
                    asm volatile(
                        "mma.sync.aligned.m16n8k16.row.col.f32.bf16.bf16.f32 "
                        "{%0,%1,%2,%3}, {%4,%5,%6,%7}, {%8,%9}, {%0,%1,%2,%3};"
                        : "+f"(acc[2*np][0]), "+f"(acc[2*np][1]),
                          "+f"(acc[2*np][2]), "+f"(acc[2*np][3])
                        : "r"(a0), "r"(a1), "r"(a2), "r"(a3), "r"(b0), "r"(b2));
                    asm volatile(
                        "mma.sync.aligned.m16n8k16.row.col.f32.bf16.bf16.f32 "
                        "{%0,%1,%2,%3}, {%4,%5,%6,%7}, {%8,%9}, {%0,%1,%2,%3};"
                        : "+f"(acc[2*np+1][0]), "+f"(acc[2*np+1][1]),
                          "+f"(acc[2*np+1][2]), "+f"(acc[2*np+1][3])
                        : "r"(a0), "r"(a1), "r"(a2), "r"(a3), "r"(b1), "r"(b3));
                }
            }
        }
        __syncthreads();
    }

    #pragma unroll
    for (int nt = 0; nt < 8; nt++) {
        size_t row = (size_t)(m0 + wid * 16 + g);
        int    col = n0 + nt * 8 + tg * 2;
        *(float2*)&C[row * 256 + col]       = make_float2(acc[nt][0], acc[nt][1]);
        *(float2*)&C[(row + 8) * 256 + col] = make_float2(acc[nt][2], acc[nt][3]);
    }
}

// ---------------------------------------------------------------------------
// Warp-cooperative sparse correction with prefix-scan gather (order = lane-
// major ascending d, identical accumulation order to R12) and MLP-4 batches.
// list: per-warp smem region of 64 ints.
__device__ __forceinline__ void sparse_corr(uint32_t fm, uint32_t sm, int lane,
                                            const float* __restrict__ Wm,
                                            int* __restrict__ list, float corr[8]) {
    int cnt = __popc(fm);
    int inc = cnt;
    #pragma unroll
    for (int off = 1; off < 32; off <<= 1) {
        int nb = __shfl_up_sync(0xffffffffu, inc, off);
        if (lane >= off) inc += nb;
    }
    int excl  = inc - cnt;
    int total = __shfl_sync(0xffffffffu, inc, 31);
    if (total > 64) total = 64;

    uint32_t f = fm;
    int o = excl;
    while (f) {
        int r = __ffs(f) - 1;
        f &= f - 1;
        if (o < 64) list[o] = (lane * 8 + r) | (((sm >> r) & 1u) << 16);
        o++;
    }
    __syncwarp();

    #pragma unroll 1
    for (int i = 0; i < total; i += 4) {
        float4 w0[4], w1[4];
        float  sg[4];
        int nb = total - i; if (nb > 4) nb = 4;
        #pragma unroll
        for (int b = 0; b < 4; b++) {
            if (b < nb) {
                int e = list[i + b];
                int d = e & 0xffff;
                sg[b] = (e >> 16) ? -1.0f : 1.0f;
                w0[b] = __ldg((const float4*)&Wm[d * 256 + lane * 8]);
                w1[b] = __ldg((const float4*)&Wm[d * 256 + lane * 8 + 4]);
            }
        }
        #pragma unroll
        for (int b = 0; b < 4; b++) {
            if (b < nb) {
                corr[0] = fmaf(sg[b], w0[b].x, corr[0]);
                corr[1] = fmaf(sg[b], w0[b].y, corr[1]);
                corr[2] = fmaf(sg[b], w0[b].z, corr[2]);
                corr[3] = fmaf(sg[b], w0[b].w, corr[3]);
                corr[4] = fmaf(sg[b], w1[b].x, corr[4]);
                corr[5] = fmaf(sg[b], w1[b].y, corr[5]);
                corr[6] = fmaf(sg[b], w1[b].z, corr[6]);
                corr[7] = fmaf(sg[b], w1[b].w, corr[7]);
            }
        }
    }
    __syncwarp();
}

// ---------------------------------------------------------------------------
// Persistent 5-step sampler: one warp per row, ALL state in registers.
// Per-element math copied verbatim from the passing R12 kernels.
__global__ __launch_bounds__(256) void ksteps(const float* __restrict__ x_in,
                                              const float* __restrict__ xa_in,
                                              const float* __restrict__ Wm,
                                              const float* __restrict__ bvec,
                                              const float* __restrict__ rr,
                                              const float* __restrict__ noise,
                                              const float* __restrict__ u,
                                              float* __restrict__ out) {
    __shared__ int listsm[8][64];
    int gwarp = (blockIdx.x * blockDim.x + threadIdx.x) >> 5;   // row
    int wslot = (threadIdx.x >> 5);
    int lane  = threadIdx.x & 31;
    if (gwarp >= B_) return;
    size_t base  = (size_t)gwarp * 256 + lane * 8;
    int    dbase = lane * 8;
    int* list = &listsm[wslot][0];

    // ---- load initial state ----
    float xa[8], vx[8], bv[8], p[8], vxd[8];
    uint32_t xmask = 0, xdmask = 0;
    {
        float xi[8], rrv[8];
        #pragma unroll
        for (int h = 0; h < 2; h++) {
            *(float4*)&xi [4*h] = __ldg((const float4*)&x_in [base + 4*h]);
            *(float4*)&xa [4*h] = __ldg((const float4*)&xa_in[base + 4*h]);
            *(float4*)&vx [4*h] = __ldg((const float4*)&g_vx [base + 4*h]);
            *(float4*)&bv [4*h] = __ldg((const float4*)&bvec [dbase + 4*h]);
            *(float4*)&rrv[4*h] = __ldg((const float4*)&rr   [base + 4*h]);
        }
        // initial proposal (phase1, bit-identical math)
        uint32_t fm = 0, sm = 0;
        #pragma unroll
        for (int j = 0; j < 8; j++) {
            float x  = xi[j];
            if (x > 0.5f) { xmask |= 1u << j; sm |= 1u << j; }
            float s  = 1.0f - 2.0f * x;
            float ga = (x - xa[j]) / 1.0e4f;
            float pp = flip_p(vx[j], bv[j], ga, s);
            p[j] = pp;
            if (rrv[j] < pp) fm |= 1u << j;
        }
        xdmask = xmask ^ fm;
        float corr[8] = {0,0,0,0,0,0,0,0};
        sparse_corr(fm, sm, lane, Wm, list, corr);
        #pragma unroll
        for (int j = 0; j < 8; j++) vxd[j] = vx[j] + corr[j];
    }

    // ---- 5 MH steps, fully in registers ----
    #pragma unroll 1
    for (int s = 0; s < NSTEPS_; s++) {
        const float* nz_s = noise + (size_t)s * BD;
        float uu = __ldg(&u[(size_t)s * B_ + gwarp]);

        float nzv[8];
        #pragma unroll
        for (int h = 0; h < 2; h++)
            *(float4*)&nzv[4*h] = __ldg((const float4*)&nz_s[base + 4*h]);

        float xdav[8], p2v[8];
        double q = 0.0;
        #pragma unroll
        for (int j = 0; j < 8; j++) {
            float x  = (float)((xmask  >> j) & 1u);
            float xd = (float)((xdmask >> j) & 1u);
            float xaj = xa[j], vxj = vx[j], vxdj = vxd[j];
            float pj = p[j], nzj = nzv[j], bvj = bv[j];

            float ga  = (x - xaj) / 1.0e4f;
            float ind = (x != xd) ? 1.0f : 0.0f;
            float xda = (xaj + 0.25f * ga) + 0.70710678118654752f * nzj;

            float s2  = 1.0f - 2.0f * xd;
            float ga2 = (xd - xda) / 1.0e4f;
            float p2  = flip_p(vxdj, bvj, ga2, s2);

            float a1 = (ind != 0.0f) ? (pj + 1e-10f) : ((1.0f - pj) + 1e-10f);
            float a2 = (ind != 0.0f) ? (p2 + 1e-10f) : ((1.0f - p2) + 1e-10f);
            float t_log = fast_log(a2) - fast_log(a1);

            float dc = x  - xaj;
            float dn = xd - xda;
            float t_m = ((0.5f * (vxdj * xd) + bvj * xd) - (dn * dn) * 5e-5f)
                      - ((0.5f * (vxj  * x ) + bvj * x ) - (dc * dc) * 5e-5f);

            float ff = xda - (xaj + 0.25f * ga);
            float fr = xaj - (xda + 0.25f * ga2);
            float t_q = ff * ff - fr * fr;

            q += (double)(t_log + t_m + t_q);

            xdav[j] = xda; p2v[j] = p2;
        }

        double la = wsumd(q);
        int accept = la > log((double)uu);

        if (accept) {
            xmask = xdmask;
            #pragma unroll
            for (int j = 0; j < 8; j++) { xa[j] = xdav[j]; vx[j] = vxd[j]; p[j] = p2v[j]; }
        }

        if (s + 1 < NSTEPS_) {
            const float* rr_n = rr + (size_t)(s + 1) * BD;
            float rrv[8];
            #pragma unroll
            for (int h = 0; h < 2; h++)
                *(float4*)&rrv[4*h] = __ldg((const float4*)&rr_n[base + 4*h]);
            uint32_t fm = 0, sm = xmask;
            #pragma unroll
            for (int j = 0; j < 8; j++)
                if (rrv[j] < p[j]) fm |= 1u << j;
            xdmask = xmask ^ fm;
            float corr[8] = {0,0,0,0,0,0,0,0};
            sparse_corr(fm, sm, lane, Wm, list, corr);
            #pragma unroll
            for (int j = 0; j < 8; j++) vxd[j] = vx[j] + corr[j];
        }
    }

    // ---- final output ----
    float o1[8];
    #pragma unroll
    for (int j = 0; j < 8; j++) o1[j] = (float)((xmask >> j) & 1u);
    #pragma unroll
    for (int h = 0; h < 2; h++) {
        *(float4*)&out[base + 4*h]      = *(float4*)&o1[4*h];
        *(float4*)&out[BD + base + 4*h] = *(float4*)&xa[4*h];
    }
}

// ---------------------------------------------------------------------------
extern "C" void kernel_launch(void* const* d_in, const int* in_sizes, int n_in,
                              void* d_out, int out_size) {
    (void)in_sizes; (void)n_in; (void)out_size;
    const float* x_in  = (const float*)d_in[0];
    const float* xa_in = (const float*)d_in[1];
    const float* Wm    = (const float*)d_in[2];
    const float* bvec  = (const float*)d_in[3];
    const float* rr    = (const float*)d_in[4];
    const float* noise = (const float*)d_in[5];
    const float* u     = (const float*)d_in[6];
    float* out = (float*)d_out;

    __nv_bfloat16* xbf_p; cudaGetSymbolAddress((void**)&xbf_p, g_xbf);
    float* vx_p;          cudaGetSymbolAddress((void**)&vx_p,  g_vx);

    kinit<<<BD / 1024, 256>>>(x_in);
    kprep<<<256, 256>>>(Wm);
    gemm_tc<<<dim3(B_ / 128, 256 / 64), 256>>>(xbf_p, vx_p);   // vx = x @ W
    ksteps<<<B_ / 8, 256>>>(x_in, xa_in, Wm, bvec, rr, noise, u, out);
}